// round 4
// baseline (speedup 1.0000x reference)
#include <cuda_runtime.h>

// ============================================================================
// Intergrator_5952824672851  (CFD cell integrator, F=6M faces, C=4M cells)
//
// per cell c, faces f0,f1,f2 = cell_face[:,c], normals n_i = unv[c,i,:]:
//   dot_i = uv[fi] . n_i
//   loss_continuity[c] = sum_i dot_i * area[fi]
//   A = sum_i uv[fi] * (dot_i * area[fi])
//   P = sum_i p[fi] * n_i * area[fi]
//   D = sum_i flux_D[fi]
//   out[c] = rhs_coef[c] * (-A - P/rho[c]) + D
//
// R3 -> R4: pack record shrunk 32B -> 16B (flux_D gathered directly from its
// input array, which fits in L2). Pack table 192MB -> 96MB for L2 residency;
// pack pass traffic 336MB -> 192MB.
// ============================================================================

#define MAX_F 6000000

// 1 float4 per face: [u, v, p, area]  -> 16B record, one sector per gather
__device__ float4 g_pack16[MAX_F];
__device__ int    g_idx_kind;   // 0 = int64, 1 = int32, 2 = float32

__global__ void detect_idx_kind_kernel(const unsigned int* __restrict__ w,
                                       long long nwords) {
    int t = threadIdx.x;
    long long stride = nwords / 128;
    if (stride < 2) stride = 2;
    long long pos = stride * (long long)t;

    bool odd_zero = true;   // int64 LE: high word of each element == 0
    bool small    = true;   // int32 indices < 2^24
    if (pos + 1 < nwords) {
        unsigned int lo = w[pos & ~1LL];
        unsigned int hi = w[pos | 1LL];
        odd_zero = (hi == 0u);
        small    = (lo < (1u << 24)) && (hi < (1u << 24) || hi == 0u);
    }
    unsigned all_oz = __ballot_sync(0xFFFFFFFFu, odd_zero);
    unsigned all_sm = __ballot_sync(0xFFFFFFFFu, small);

    __shared__ unsigned s_oz[4], s_sm[4];
    int wid = t >> 5;
    if ((t & 31) == 0) { s_oz[wid] = all_oz; s_sm[wid] = all_sm; }
    __syncthreads();
    if (t == 0) {
        bool oz = (s_oz[0] & s_oz[1] & s_oz[2] & s_oz[3]) == 0xFFFFFFFFu;
        bool sm = (s_sm[0] & s_sm[1] & s_sm[2] & s_sm[3]) == 0xFFFFFFFFu;
        g_idx_kind = oz ? 0 : (sm ? 1 : 2);
    }
}

__global__ void __launch_bounds__(256)
pack_faces_kernel(const float2* __restrict__ uv_face,
                  const float*  __restrict__ p_face,
                  const float*  __restrict__ face_area,
                  int F) {
    int f = blockIdx.x * blockDim.x + threadIdx.x;
    if (f >= F) return;
    float2 uv = uv_face[f];
    float  p  = p_face[f];
    float  a  = face_area[f];
    g_pack16[f] = make_float4(uv.x, uv.y, p, a);
}

__device__ __forceinline__ long long load_idx(const void* p, int kind, long long i) {
    if (kind == 0) return ((const long long*)p)[i];
    if (kind == 1) return (long long)(((const int*)p)[i]);
    return (long long)(((const float*)p)[i]);
}

__device__ __forceinline__ long long clampF(long long v, long long F) {
    if (v < 0) v = 0;
    if (v >= F) v = F - 1;
    return v;
}

__global__ void __launch_bounds__(256)
cell_integrate_kernel(const void*   __restrict__ cell_face, // [3, C]
                      const float2* __restrict__ flux_D,    // [F] float2
                      const float2* __restrict__ unv,       // [C,3,2]
                      const float*  __restrict__ rho,       // [C]
                      const float*  __restrict__ rhs_coef,  // [C]
                      float*        __restrict__ out,       // [3C]
                      int C, int F) {
    int c = blockIdx.x * blockDim.x + threadIdx.x;
    if (c >= C) return;

    int kind = g_idx_kind;  // grid-uniform, cached

    long long cf0 = clampF(load_idx(cell_face, kind, c), F);
    long long cf1 = clampF(load_idx(cell_face, kind, (long long)C + c), F);
    long long cf2 = clampF(load_idx(cell_face, kind, 2LL * C + c), F);

    // Issue all 6 gathers up-front (independent -> MLP)
    float4 a0 = g_pack16[cf0];
    float4 a1 = g_pack16[cf1];
    float4 a2 = g_pack16[cf2];
    float2 b0 = flux_D[cf0];
    float2 b1 = flux_D[cf1];
    float2 b2 = flux_D[cf2];

    float2 n0 = unv[3 * c + 0];
    float2 n1 = unv[3 * c + 1];
    float2 n2 = unv[3 * c + 2];

    float dot0 = a0.x * n0.x + a0.y * n0.y;
    float de0  = dot0 * a0.w;
    float pe0  = a0.z * a0.w;
    float dot1 = a1.x * n1.x + a1.y * n1.y;
    float de1  = dot1 * a1.w;
    float pe1  = a1.z * a1.w;
    float dot2 = a2.x * n2.x + a2.y * n2.y;
    float de2  = dot2 * a2.w;
    float pe2  = a2.z * a2.w;

    float loss = de0 + de1 + de2;

    float Ax = a0.x * de0 + a1.x * de1 + a2.x * de2;
    float Ay = a0.y * de0 + a1.y * de1 + a2.y * de2;

    float Px = pe0 * n0.x + pe1 * n1.x + pe2 * n2.x;
    float Py = pe0 * n0.y + pe1 * n1.y + pe2 * n2.y;

    float Dx = b0.x + b1.x + b2.x;
    float Dy = b0.y + b1.y + b2.y;

    float inv_rho = 1.0f / rho[c];
    float rc = rhs_coef[c];

    float ox = rc * (-Ax - inv_rho * Px) + Dx;
    float oy = rc * (-Ay - inv_rho * Py) + Dy;

    out[c] = loss;                                // loss_continuity [C,1]
    float2* o2 = reinterpret_cast<float2*>(out + C);
    o2[c] = make_float2(ox, oy);                  // out [C,2]
}

extern "C" void kernel_launch(void* const* d_in, const int* in_sizes, int n_in,
                              void* d_out, int out_size) {
    // 0 uv_face [F,2] f32 | 1 p_face [F,1] f32 | 2 flux_D [F,2] f32
    // 3 unv [C,3,2] f32   | 4 rho [C,1] f32    | 5 rhs_coef [C,1] f32
    // 6 face_area [F,1] f32 | 7 cell_face [3,C] (int64 or downcast)
    const float2* uv_face   = (const float2*)d_in[0];
    const float*  p_face    = (const float*) d_in[1];
    const float2* flux_D    = (const float2*)d_in[2];
    const float2* unv       = (const float2*)d_in[3];
    const float*  rho       = (const float*) d_in[4];
    const float*  rhs_coef  = (const float*) d_in[5];
    const float*  face_area = (const float*) d_in[6];
    const void*   cell_face = d_in[7];

    int F = in_sizes[1];   // p_face element count
    int C = in_sizes[4];   // rho element count
    float* out = (float*)d_out;

    long long nwords = 3LL * C;  // safe lower bound on 32-bit word count

    const int TPB = 256;
    detect_idx_kind_kernel<<<1, 128>>>((const unsigned int*)cell_face, nwords);
    pack_faces_kernel<<<(F + TPB - 1) / TPB, TPB>>>(uv_face, p_face, face_area, F);
    cell_integrate_kernel<<<(C + TPB - 1) / TPB, TPB>>>(cell_face, flux_D, unv,
                                                        rho, rhs_coef, out, C, F);
}

// round 6
// speedup vs baseline: 1.0536x; 1.0536x over previous
#include <cuda_runtime.h>

// ============================================================================
// Intergrator_5952824672851  (CFD cell integrator, F=6M faces, C=4M cells)
//
// per cell c, faces f0,f1,f2 = cell_face[:,c], normals n_i = unv[c,i,:]:
//   dot_i = uv[fi] . n_i
//   loss_continuity[c] = sum_i dot_i * area[fi]
//   A = sum_i uv[fi] * (dot_i * area[fi])
//   P = sum_i p[fi] * n_i * area[fi]
//   D = sum_i flux_D[fi]
//   out[c] = rhs_coef[c] * (-A - P/rho[c]) + D
//
// R5 -> R6: fixed divergent __syncthreads() in pack kernel block 0 (two
// barrier call sites in divergent branches -> possible deadlock / container
// timeout). Detection now uses one uniform barrier for all of block 0.
// Rest of R5 kept: 32B record (one random sector per face gather), 24B
// stores, 2 cells/thread for gather MLP, __ldcg gathers.
// ============================================================================

#define MAX_F 6000000

// 32B-stride record per face: [u, v, p, area][fDx, fDy, pad, pad]
__device__ float4 g_pack[2 * MAX_F];
__device__ int    g_idx_kind;   // 0 = int64, 1 = int32, 2 = float32

__global__ void __launch_bounds__(256)
pack_faces_kernel(const float2* __restrict__ uv_face,
                  const float*  __restrict__ p_face,
                  const float2* __restrict__ flux_D,
                  const float*  __restrict__ face_area,
                  const unsigned int* __restrict__ idx_words,
                  long long nwords,
                  int F) {
    // --- dtype detection folded into block 0; barrier is block-uniform ---
    if (blockIdx.x == 0) {
        __shared__ unsigned s_oz[4], s_sm[4];
        int t = threadIdx.x;
        if (t < 128) {  // warps 0-3 only; warp-uniform branch
            long long stride = nwords / 128;
            if (stride < 2) stride = 2;
            long long pos = stride * (long long)t;
            bool odd_zero = true;   // int64 LE: high word == 0
            bool small    = true;   // int32 indices < 2^24
            if (pos + 1 < nwords) {
                unsigned int lo = idx_words[pos & ~1LL];
                unsigned int hi = idx_words[pos | 1LL];
                odd_zero = (hi == 0u);
                small    = (lo < (1u << 24)) && (hi < (1u << 24) || hi == 0u);
            }
            unsigned all_oz = __ballot_sync(0xFFFFFFFFu, odd_zero);
            unsigned all_sm = __ballot_sync(0xFFFFFFFFu, small);
            if ((t & 31) == 0) { s_oz[t >> 5] = all_oz; s_sm[t >> 5] = all_sm; }
        }
        __syncthreads();   // single call site, all 256 threads of block 0
        if (t == 0) {
            bool oz = (s_oz[0] & s_oz[1] & s_oz[2] & s_oz[3]) == 0xFFFFFFFFu;
            bool sm = (s_sm[0] & s_sm[1] & s_sm[2] & s_sm[3]) == 0xFFFFFFFFu;
            g_idx_kind = oz ? 0 : (sm ? 1 : 2);
        }
    }

    int f = blockIdx.x * blockDim.x + threadIdx.x;
    if (f >= F) return;
    float2 uv = uv_face[f];
    float2 fd = flux_D[f];
    float  p  = p_face[f];
    float  a  = face_area[f];
    g_pack[2 * f] = make_float4(uv.x, uv.y, p, a);
    // store only the 8 meaningful bytes of the second half (skip padding)
    *reinterpret_cast<float2*>(&g_pack[2 * f + 1]) = fd;
}

__device__ __forceinline__ long long load_idx(const void* p, int kind, long long i) {
    if (kind == 0) return ((const long long*)p)[i];
    if (kind == 1) return (long long)(((const int*)p)[i]);
    return (long long)(((const float*)p)[i]);
}

__device__ __forceinline__ long long clampF(long long v, long long F) {
    if (v < 0) v = 0;
    if (v >= F) v = F - 1;
    return v;
}

struct CellOut { float loss, ox, oy; };

__device__ __forceinline__ CellOut do_cell(float2 n0, float2 n1, float2 n2,
                                           float rho_c, float rc,
                                           float4 a0, float2 b0,
                                           float4 a1, float2 b1,
                                           float4 a2, float2 b2) {
    float dot0 = a0.x * n0.x + a0.y * n0.y;
    float de0  = dot0 * a0.w;
    float pe0  = a0.z * a0.w;
    float dot1 = a1.x * n1.x + a1.y * n1.y;
    float de1  = dot1 * a1.w;
    float pe1  = a1.z * a1.w;
    float dot2 = a2.x * n2.x + a2.y * n2.y;
    float de2  = dot2 * a2.w;
    float pe2  = a2.z * a2.w;

    CellOut r;
    r.loss = de0 + de1 + de2;

    float Ax = a0.x * de0 + a1.x * de1 + a2.x * de2;
    float Ay = a0.y * de0 + a1.y * de1 + a2.y * de2;
    float Px = pe0 * n0.x + pe1 * n1.x + pe2 * n2.x;
    float Py = pe0 * n0.y + pe1 * n1.y + pe2 * n2.y;
    float Dx = b0.x + b1.x + b2.x;
    float Dy = b0.y + b1.y + b2.y;

    float inv_rho = 1.0f / rho_c;
    r.ox = rc * (-Ax - inv_rho * Px) + Dx;
    r.oy = rc * (-Ay - inv_rho * Py) + Dy;
    return r;
}

__global__ void __launch_bounds__(256)
cell_integrate_kernel(const void*   __restrict__ cell_face, // [3, C]
                      const float2* __restrict__ unv,       // [C,3,2]
                      const float*  __restrict__ rho,       // [C]
                      const float*  __restrict__ rhs_coef,  // [C]
                      float*        __restrict__ out,       // [3C]
                      int C, int F) {
    int idx  = blockIdx.x * blockDim.x + threadIdx.x;
    int half = (C + 1) / 2;
    if (idx >= half) return;

    int kind = g_idx_kind;
    int cA = idx;
    int cB = idx + half;          // second cell (may be out of range when C odd)
    bool hasB = (cB < C);

    // ---- indices for both cells (6 loads, independent) ----
    long long fA0 = clampF(load_idx(cell_face, kind, cA), F);
    long long fA1 = clampF(load_idx(cell_face, kind, (long long)C + cA), F);
    long long fA2 = clampF(load_idx(cell_face, kind, 2LL * C + cA), F);
    long long fB0 = hasB ? clampF(load_idx(cell_face, kind, cB), F) : 0;
    long long fB1 = hasB ? clampF(load_idx(cell_face, kind, (long long)C + cB), F) : 0;
    long long fB2 = hasB ? clampF(load_idx(cell_face, kind, 2LL * C + cB), F) : 0;

    // ---- 12 gathers issued back-to-back (6 random sectors in flight) ----
    float4 aA0 = __ldcg(&g_pack[2 * fA0]);
    float2 bA0 = __ldcg(reinterpret_cast<const float2*>(&g_pack[2 * fA0 + 1]));
    float4 aA1 = __ldcg(&g_pack[2 * fA1]);
    float2 bA1 = __ldcg(reinterpret_cast<const float2*>(&g_pack[2 * fA1 + 1]));
    float4 aA2 = __ldcg(&g_pack[2 * fA2]);
    float2 bA2 = __ldcg(reinterpret_cast<const float2*>(&g_pack[2 * fA2 + 1]));
    float4 aB0 = __ldcg(&g_pack[2 * fB0]);
    float2 bB0 = __ldcg(reinterpret_cast<const float2*>(&g_pack[2 * fB0 + 1]));
    float4 aB1 = __ldcg(&g_pack[2 * fB1]);
    float2 bB1 = __ldcg(reinterpret_cast<const float2*>(&g_pack[2 * fB1 + 1]));
    float4 aB2 = __ldcg(&g_pack[2 * fB2]);
    float2 bB2 = __ldcg(reinterpret_cast<const float2*>(&g_pack[2 * fB2 + 1]));

    // ---- contiguous per-cell data ----
    float2 nA0 = unv[3 * cA + 0];
    float2 nA1 = unv[3 * cA + 1];
    float2 nA2 = unv[3 * cA + 2];
    float rhoA = rho[cA];
    float rcA  = rhs_coef[cA];

    CellOut rA = do_cell(nA0, nA1, nA2, rhoA, rcA,
                         aA0, bA0, aA1, bA1, aA2, bA2);
    out[cA] = rA.loss;
    float2* o2 = reinterpret_cast<float2*>(out + C);
    o2[cA] = make_float2(rA.ox, rA.oy);

    if (hasB) {
        float2 nB0 = unv[3 * cB + 0];
        float2 nB1 = unv[3 * cB + 1];
        float2 nB2 = unv[3 * cB + 2];
        float rhoB = rho[cB];
        float rcB  = rhs_coef[cB];
        CellOut rB = do_cell(nB0, nB1, nB2, rhoB, rcB,
                             aB0, bB0, aB1, bB1, aB2, bB2);
        out[cB] = rB.loss;
        o2[cB] = make_float2(rB.ox, rB.oy);
    }
}

extern "C" void kernel_launch(void* const* d_in, const int* in_sizes, int n_in,
                              void* d_out, int out_size) {
    // 0 uv_face [F,2] f32 | 1 p_face [F,1] f32 | 2 flux_D [F,2] f32
    // 3 unv [C,3,2] f32   | 4 rho [C,1] f32    | 5 rhs_coef [C,1] f32
    // 6 face_area [F,1] f32 | 7 cell_face [3,C] (int64 or downcast)
    const float2* uv_face   = (const float2*)d_in[0];
    const float*  p_face    = (const float*) d_in[1];
    const float2* flux_D    = (const float2*)d_in[2];
    const float2* unv       = (const float2*)d_in[3];
    const float*  rho       = (const float*) d_in[4];
    const float*  rhs_coef  = (const float*) d_in[5];
    const float*  face_area = (const float*) d_in[6];
    const void*   cell_face = d_in[7];

    int F = in_sizes[1];   // p_face element count
    int C = in_sizes[4];   // rho element count
    float* out = (float*)d_out;

    long long nwords = 3LL * C;  // safe lower bound on 32-bit word count

    const int TPB = 256;
    pack_faces_kernel<<<(F + TPB - 1) / TPB, TPB>>>(uv_face, p_face, flux_D, face_area,
                                                    (const unsigned int*)cell_face,
                                                    nwords, F);
    int half = (C + 1) / 2;
    cell_integrate_kernel<<<(half + TPB - 1) / TPB, TPB>>>(cell_face, unv, rho, rhs_coef,
                                                           out, C, F);
}

// round 8
// speedup vs baseline: 1.8530x; 1.7588x over previous
#include <cuda_runtime.h>
#include <cuda_fp16.h>

// ============================================================================
// Intergrator_5952824672851  (CFD cell integrator, F=6M faces, C=4M cells)
//
// per cell c, faces f0,f1,f2 = cell_face[:,c], normals n_i = unv[c,i,:]:
//   de_i = (uv_i . n_i) * area_i
//   loss[c] = sum_i de_i
//   A = sum_i uv_i * de_i ;  P = sum_i p_i*area_i * n_i ;  D = sum_i fD_i
//   out[c] = rhs_coef[c] * (-A - P/rho[c]) + D
//
// R7 -> R8: same 16B-record design (96MB table -> L2-resident gathers);
// removed all pointer-aliasing type puns -- fp16 pack/unpack now via
// __halves2half2 / __low2float / __high2float and uint bit intrinsics only.
//   rec = { wx=a*u (f32), wy=a*v (f32), [q=p*a | inva=1/a] (f16x2 bits),
//           [fDx | fDy] (f16x2 bits) }
//   de = w.n (fp32-exact loss path); A = sum w*(de*inva); P = sum q*n.
// ============================================================================

#define MAX_F 6000000

__device__ float4 g_rec[MAX_F];   // 96 MB table, one 32B-sector touch per gather
__device__ int    g_idx_kind;     // 0 = int64, 1 = int32, 2 = float32

__device__ __forceinline__ unsigned pack_h2(float lo, float hi) {
    __half2 h = __halves2half2(__float2half_rn(lo), __float2half_rn(hi));
    return (unsigned)__half_as_ushort(__low2half(h)) |
           ((unsigned)__half_as_ushort(__high2half(h)) << 16);
}

__device__ __forceinline__ float unpack_lo(unsigned v) {
    return __half2float(__ushort_as_half((unsigned short)(v & 0xFFFFu)));
}
__device__ __forceinline__ float unpack_hi(unsigned v) {
    return __half2float(__ushort_as_half((unsigned short)(v >> 16)));
}

__global__ void __launch_bounds__(256)
pack_faces_kernel(const float2* __restrict__ uv_face,
                  const float*  __restrict__ p_face,
                  const float2* __restrict__ flux_D,
                  const float*  __restrict__ face_area,
                  const unsigned int* __restrict__ idx_words,
                  long long nwords,
                  int F) {
    // --- dtype detection folded into block 0; single uniform barrier ---
    if (blockIdx.x == 0) {
        __shared__ unsigned s_oz[4], s_sm[4];
        int t = threadIdx.x;
        if (t < 128) {  // warps 0-3, warp-uniform
            long long stride = nwords / 128;
            if (stride < 2) stride = 2;
            long long pos = stride * (long long)t;
            bool odd_zero = true;   // int64 LE: high word == 0
            bool small    = true;   // int32 indices < 2^24
            if (pos + 1 < nwords) {
                unsigned int lo = idx_words[pos & ~1LL];
                unsigned int hi = idx_words[pos | 1LL];
                odd_zero = (hi == 0u);
                small    = (lo < (1u << 24)) && (hi < (1u << 24) || hi == 0u);
            }
            unsigned all_oz = __ballot_sync(0xFFFFFFFFu, odd_zero);
            unsigned all_sm = __ballot_sync(0xFFFFFFFFu, small);
            if ((t & 31) == 0) { s_oz[t >> 5] = all_oz; s_sm[t >> 5] = all_sm; }
        }
        __syncthreads();
        if (t == 0) {
            bool oz = (s_oz[0] & s_oz[1] & s_oz[2] & s_oz[3]) == 0xFFFFFFFFu;
            bool sm = (s_sm[0] & s_sm[1] & s_sm[2] & s_sm[3]) == 0xFFFFFFFFu;
            g_idx_kind = oz ? 0 : (sm ? 1 : 2);
        }
    }

    int f = blockIdx.x * blockDim.x + threadIdx.x;
    if (f >= F) return;
    float2 uv = uv_face[f];
    float2 fd = flux_D[f];
    float  p  = p_face[f];
    float  a  = face_area[f];

    float wx   = a * uv.x;
    float wy   = a * uv.y;
    float q    = p * a;
    float inva = fminf(1.0f / fmaxf(a, 1e-30f), 65000.0f);  // safe, tiny-a faces ~0 anyway

    float4 rec;
    rec.x = wx;
    rec.y = wy;
    rec.z = __uint_as_float(pack_h2(q, inva));
    rec.w = __uint_as_float(pack_h2(fd.x, fd.y));
    g_rec[f] = rec;
}

__device__ __forceinline__ long long load_idx(const void* p, int kind, long long i) {
    if (kind == 0) return ((const long long*)p)[i];
    if (kind == 1) return (long long)(((const int*)p)[i]);
    return (long long)(((const float*)p)[i]);
}

__device__ __forceinline__ long long clampF(long long v, long long F) {
    if (v < 0) v = 0;
    if (v >= F) v = F - 1;
    return v;
}

__global__ void __launch_bounds__(256)
cell_integrate_kernel(const void*   __restrict__ cell_face, // [3, C]
                      const float2* __restrict__ unv,       // [C,3,2]
                      const float*  __restrict__ rho,       // [C]
                      const float*  __restrict__ rhs_coef,  // [C]
                      float*        __restrict__ out,       // [3C]
                      int C, int F) {
    int c = blockIdx.x * blockDim.x + threadIdx.x;
    if (c >= C) return;

    int kind = g_idx_kind;

    long long f0 = clampF(load_idx(cell_face, kind, c), F);
    long long f1 = clampF(load_idx(cell_face, kind, (long long)C + c), F);
    long long f2 = clampF(load_idx(cell_face, kind, 2LL * C + c), F);

    // 3 random gathers, one 32B sector each, issued back-to-back
    float4 r0 = __ldcg(&g_rec[f0]);
    float4 r1 = __ldcg(&g_rec[f1]);
    float4 r2 = __ldcg(&g_rec[f2]);

    float2 n0 = unv[3 * c + 0];
    float2 n1 = unv[3 * c + 1];
    float2 n2 = unv[3 * c + 2];

    unsigned z0 = __float_as_uint(r0.z), w0 = __float_as_uint(r0.w);
    unsigned z1 = __float_as_uint(r1.z), w1 = __float_as_uint(r1.w);
    unsigned z2 = __float_as_uint(r2.z), w2 = __float_as_uint(r2.w);

    float q0 = unpack_lo(z0), ia0 = unpack_hi(z0);
    float q1 = unpack_lo(z1), ia1 = unpack_hi(z1);
    float q2 = unpack_lo(z2), ia2 = unpack_hi(z2);
    float fdx0 = unpack_lo(w0), fdy0 = unpack_hi(w0);
    float fdx1 = unpack_lo(w1), fdy1 = unpack_hi(w1);
    float fdx2 = unpack_lo(w2), fdy2 = unpack_hi(w2);

    // de_i = w_i . n_i  == (uv.n)*area, fp32-exact path
    float de0 = r0.x * n0.x + r0.y * n0.y;
    float de1 = r1.x * n1.x + r1.y * n1.y;
    float de2 = r2.x * n2.x + r2.y * n2.y;

    float loss = de0 + de1 + de2;

    float s0 = de0 * ia0;     // de * (1/area)
    float s1 = de1 * ia1;
    float s2 = de2 * ia2;

    float Ax = r0.x * s0 + r1.x * s1 + r2.x * s2;   // sum uv*de  (w/area = uv)
    float Ay = r0.y * s0 + r1.y * s1 + r2.y * s2;

    float Px = q0 * n0.x + q1 * n1.x + q2 * n2.x;
    float Py = q0 * n0.y + q1 * n1.y + q2 * n2.y;

    float Dx = fdx0 + fdx1 + fdx2;
    float Dy = fdy0 + fdy1 + fdy2;

    float inv_rho = 1.0f / rho[c];
    float rc = rhs_coef[c];

    float ox = rc * (-Ax - inv_rho * Px) + Dx;
    float oy = rc * (-Ay - inv_rho * Py) + Dy;

    out[c] = loss;                                // loss_continuity [C,1]
    float2* o2 = reinterpret_cast<float2*>(out + C);
    o2[c] = make_float2(ox, oy);                  // out [C,2]
}

extern "C" void kernel_launch(void* const* d_in, const int* in_sizes, int n_in,
                              void* d_out, int out_size) {
    // 0 uv_face [F,2] f32 | 1 p_face [F,1] f32 | 2 flux_D [F,2] f32
    // 3 unv [C,3,2] f32   | 4 rho [C,1] f32    | 5 rhs_coef [C,1] f32
    // 6 face_area [F,1] f32 | 7 cell_face [3,C] (int64 or downcast)
    const float2* uv_face   = (const float2*)d_in[0];
    const float*  p_face    = (const float*) d_in[1];
    const float2* flux_D    = (const float2*)d_in[2];
    const float2* unv       = (const float2*)d_in[3];
    const float*  rho       = (const float*) d_in[4];
    const float*  rhs_coef  = (const float*) d_in[5];
    const float*  face_area = (const float*) d_in[6];
    const void*   cell_face = d_in[7];

    int F = in_sizes[1];   // p_face element count
    int C = in_sizes[4];   // rho element count
    float* out = (float*)d_out;

    long long nwords = 3LL * C;  // safe lower bound on 32-bit word count

    const int TPB = 256;
    pack_faces_kernel<<<(F + TPB - 1) / TPB, TPB>>>(uv_face, p_face, flux_D, face_area,
                                                    (const unsigned int*)cell_face,
                                                    nwords, F);
    cell_integrate_kernel<<<(C + TPB - 1) / TPB, TPB>>>(cell_face, unv, rho, rhs_coef,
                                                        out, C, F);
}

// round 9
// speedup vs baseline: 2.0537x; 1.1083x over previous
#include <cuda_runtime.h>
#include <cuda_fp16.h>

// ============================================================================
// Intergrator_5952824672851  (CFD cell integrator, F=6M faces, C=4M cells)
//
// per cell c, faces f0,f1,f2 = cell_face[:,c], normals n_i = unv[c,i,:]:
//   de_i = (uv_i . n_i) * area_i
//   loss[c] = sum_i de_i
//   A = sum_i uv_i * de_i ;  P = sum_i p_i*area_i * n_i ;  D = sum_i fD_i
//   out[c] = rhs_coef[c] * (-A - P/rho[c]) + D
//
// R8 -> R9: cache-priority separation. The 96MB record table is the only
// reused data; all contiguous streams are single-use. Streaming accesses now
// use evict-first hints (__ldcs/__stcs) so the table stays L2-resident:
//   - measured R8: gathers cost ~478MB DRAM (40%% hit). With the table
//     protected, gathers should mostly hit the (dirty, just-written) lines.
// Record layout unchanged: { wx=a*u f32, wy=a*v f32, [q|inva] f16x2,
//                            [fDx|fDy] f16x2 } = 16B, one sector per gather.
// ============================================================================

#define MAX_F 6000000

__device__ float4 g_rec[MAX_F];   // 96 MB table, one 32B-sector touch per gather
__device__ int    g_idx_kind;     // 0 = int64, 1 = int32, 2 = float32

__device__ __forceinline__ unsigned pack_h2(float lo, float hi) {
    __half2 h = __halves2half2(__float2half_rn(lo), __float2half_rn(hi));
    return (unsigned)__half_as_ushort(__low2half(h)) |
           ((unsigned)__half_as_ushort(__high2half(h)) << 16);
}

__device__ __forceinline__ float unpack_lo(unsigned v) {
    return __half2float(__ushort_as_half((unsigned short)(v & 0xFFFFu)));
}
__device__ __forceinline__ float unpack_hi(unsigned v) {
    return __half2float(__ushort_as_half((unsigned short)(v >> 16)));
}

__global__ void __launch_bounds__(256)
pack_faces_kernel(const float2* __restrict__ uv_face,
                  const float*  __restrict__ p_face,
                  const float2* __restrict__ flux_D,
                  const float*  __restrict__ face_area,
                  const unsigned int* __restrict__ idx_words,
                  long long nwords,
                  int F) {
    // --- dtype detection folded into block 0; single uniform barrier ---
    if (blockIdx.x == 0) {
        __shared__ unsigned s_oz[4], s_sm[4];
        int t = threadIdx.x;
        if (t < 128) {  // warps 0-3, warp-uniform
            long long stride = nwords / 128;
            if (stride < 2) stride = 2;
            long long pos = stride * (long long)t;
            bool odd_zero = true;   // int64 LE: high word == 0
            bool small    = true;   // int32 indices < 2^24
            if (pos + 1 < nwords) {
                unsigned int lo = idx_words[pos & ~1LL];
                unsigned int hi = idx_words[pos | 1LL];
                odd_zero = (hi == 0u);
                small    = (lo < (1u << 24)) && (hi < (1u << 24) || hi == 0u);
            }
            unsigned all_oz = __ballot_sync(0xFFFFFFFFu, odd_zero);
            unsigned all_sm = __ballot_sync(0xFFFFFFFFu, small);
            if ((t & 31) == 0) { s_oz[t >> 5] = all_oz; s_sm[t >> 5] = all_sm; }
        }
        __syncthreads();
        if (t == 0) {
            bool oz = (s_oz[0] & s_oz[1] & s_oz[2] & s_oz[3]) == 0xFFFFFFFFu;
            bool sm = (s_sm[0] & s_sm[1] & s_sm[2] & s_sm[3]) == 0xFFFFFFFFu;
            g_idx_kind = oz ? 0 : (sm ? 1 : 2);
        }
    }

    int f = blockIdx.x * blockDim.x + threadIdx.x;
    if (f >= F) return;
    // streaming reads: evict-first, don't pollute L2
    float2 uv = __ldcs(&uv_face[f]);
    float2 fd = __ldcs(&flux_D[f]);
    float  p  = __ldcs(&p_face[f]);
    float  a  = __ldcs(&face_area[f]);

    float wx   = a * uv.x;
    float wy   = a * uv.y;
    float q    = p * a;
    float inva = fminf(1.0f / fmaxf(a, 1e-30f), 65000.0f);

    float4 rec;
    rec.x = wx;
    rec.y = wy;
    rec.z = __uint_as_float(pack_h2(q, inva));
    rec.w = __uint_as_float(pack_h2(fd.x, fd.y));
    g_rec[f] = rec;   // normal priority: leave table lines resident in L2
}

__device__ __forceinline__ long long load_idx_cs(const void* p, int kind, long long i) {
    if (kind == 0) return __ldcs(&((const long long*)p)[i]);
    if (kind == 1) return (long long)__ldcs(&((const int*)p)[i]);
    return (long long)__ldcs(&((const float*)p)[i]);
}

__device__ __forceinline__ long long clampF(long long v, long long F) {
    if (v < 0) v = 0;
    if (v >= F) v = F - 1;
    return v;
}

__global__ void __launch_bounds__(256)
cell_integrate_kernel(const void*   __restrict__ cell_face, // [3, C]
                      const float2* __restrict__ unv,       // [C,3,2]
                      const float*  __restrict__ rho,       // [C]
                      const float*  __restrict__ rhs_coef,  // [C]
                      float*        __restrict__ out,       // [3C]
                      int C, int F) {
    int c = blockIdx.x * blockDim.x + threadIdx.x;
    if (c >= C) return;

    int kind = g_idx_kind;

    long long f0 = clampF(load_idx_cs(cell_face, kind, c), F);
    long long f1 = clampF(load_idx_cs(cell_face, kind, (long long)C + c), F);
    long long f2 = clampF(load_idx_cs(cell_face, kind, 2LL * C + c), F);

    // 3 random gathers, one 32B sector each; normal L2 priority (reused data)
    float4 r0 = __ldcg(&g_rec[f0]);
    float4 r1 = __ldcg(&g_rec[f1]);
    float4 r2 = __ldcg(&g_rec[f2]);

    // streaming per-cell data: evict-first
    float2 n0 = __ldcs(&unv[3 * c + 0]);
    float2 n1 = __ldcs(&unv[3 * c + 1]);
    float2 n2 = __ldcs(&unv[3 * c + 2]);

    unsigned z0 = __float_as_uint(r0.z), w0 = __float_as_uint(r0.w);
    unsigned z1 = __float_as_uint(r1.z), w1 = __float_as_uint(r1.w);
    unsigned z2 = __float_as_uint(r2.z), w2 = __float_as_uint(r2.w);

    float q0 = unpack_lo(z0), ia0 = unpack_hi(z0);
    float q1 = unpack_lo(z1), ia1 = unpack_hi(z1);
    float q2 = unpack_lo(z2), ia2 = unpack_hi(z2);
    float fdx0 = unpack_lo(w0), fdy0 = unpack_hi(w0);
    float fdx1 = unpack_lo(w1), fdy1 = unpack_hi(w1);
    float fdx2 = unpack_lo(w2), fdy2 = unpack_hi(w2);

    // de_i = w_i . n_i == (uv.n)*area, fp32-exact path
    float de0 = r0.x * n0.x + r0.y * n0.y;
    float de1 = r1.x * n1.x + r1.y * n1.y;
    float de2 = r2.x * n2.x + r2.y * n2.y;

    float loss = de0 + de1 + de2;

    float s0 = de0 * ia0;     // de * (1/area)
    float s1 = de1 * ia1;
    float s2 = de2 * ia2;

    float Ax = r0.x * s0 + r1.x * s1 + r2.x * s2;   // sum uv*de  (w/area = uv)
    float Ay = r0.y * s0 + r1.y * s1 + r2.y * s2;

    float Px = q0 * n0.x + q1 * n1.x + q2 * n2.x;
    float Py = q0 * n0.y + q1 * n1.y + q2 * n2.y;

    float Dx = fdx0 + fdx1 + fdx2;
    float Dy = fdy0 + fdy1 + fdy2;

    float inv_rho = 1.0f / __ldcs(&rho[c]);
    float rc = __ldcs(&rhs_coef[c]);

    float ox = rc * (-Ax - inv_rho * Px) + Dx;
    float oy = rc * (-Ay - inv_rho * Py) + Dy;

    // streaming writes: evict-first
    __stcs(&out[c], loss);                            // loss_continuity [C,1]
    float2* o2 = reinterpret_cast<float2*>(out + C);
    __stcs(&o2[c], make_float2(ox, oy));              // out [C,2]
}

extern "C" void kernel_launch(void* const* d_in, const int* in_sizes, int n_in,
                              void* d_out, int out_size) {
    // 0 uv_face [F,2] f32 | 1 p_face [F,1] f32 | 2 flux_D [F,2] f32
    // 3 unv [C,3,2] f32   | 4 rho [C,1] f32    | 5 rhs_coef [C,1] f32
    // 6 face_area [F,1] f32 | 7 cell_face [3,C] (int64 or downcast)
    const float2* uv_face   = (const float2*)d_in[0];
    const float*  p_face    = (const float*) d_in[1];
    const float2* flux_D    = (const float2*)d_in[2];
    const float2* unv       = (const float2*)d_in[3];
    const float*  rho       = (const float*) d_in[4];
    const float*  rhs_coef  = (const float*) d_in[5];
    const float*  face_area = (const float*) d_in[6];
    const void*   cell_face = d_in[7];

    int F = in_sizes[1];   // p_face element count
    int C = in_sizes[4];   // rho element count
    float* out = (float*)d_out;

    long long nwords = 3LL * C;  // safe lower bound on 32-bit word count

    const int TPB = 256;
    pack_faces_kernel<<<(F + TPB - 1) / TPB, TPB>>>(uv_face, p_face, flux_D, face_area,
                                                    (const unsigned int*)cell_face,
                                                    nwords, F);
    cell_integrate_kernel<<<(C + TPB - 1) / TPB, TPB>>>(cell_face, unv, rho, rhs_coef,
                                                        out, C, F);
}

// round 10
// speedup vs baseline: 2.0768x; 1.0113x over previous
#include <cuda_runtime.h>
#include <cuda_fp16.h>

// ============================================================================
// Intergrator_5952824672851  (CFD cell integrator, F=6M faces, C=4M cells)
//
// per cell c, faces f0,f1,f2 = cell_face[:,c], normals n_i = unv[c,i,:]:
//   de_i = (uv_i . n_i) * area_i
//   loss[c] = sum_i de_i
//   A = sum_i uv_i * de_i ;  P = sum_i p_i*area_i * n_i ;  D = sum_i fD_i
//   out[c] = rhs_coef[c] * (-A - P/rho[c]) + D
//
// R9 -> R10: 2 ADJACENT cells per thread. All contiguous streams become
// vector loads (unv: 3x float4, cell_face: longlong2/int2, rho/rhs: float2,
// out: float2 + float4); 6 independent gathers in flight per thread.
// Record layout (16B, one sector/gather) and cache policy (.cs streams,
// .cg gathers) unchanged from R9.
// ============================================================================

#define MAX_F 6000000

__device__ float4 g_rec[MAX_F];   // 96 MB table
__device__ int    g_idx_kind;     // 0 = int64, 1 = int32, 2 = float32

__device__ __forceinline__ unsigned pack_h2(float lo, float hi) {
    __half2 h = __halves2half2(__float2half_rn(lo), __float2half_rn(hi));
    return (unsigned)__half_as_ushort(__low2half(h)) |
           ((unsigned)__half_as_ushort(__high2half(h)) << 16);
}
__device__ __forceinline__ float unpack_lo(unsigned v) {
    return __half2float(__ushort_as_half((unsigned short)(v & 0xFFFFu)));
}
__device__ __forceinline__ float unpack_hi(unsigned v) {
    return __half2float(__ushort_as_half((unsigned short)(v >> 16)));
}

__global__ void __launch_bounds__(256)
pack_faces_kernel(const float2* __restrict__ uv_face,
                  const float*  __restrict__ p_face,
                  const float2* __restrict__ flux_D,
                  const float*  __restrict__ face_area,
                  const unsigned int* __restrict__ idx_words,
                  long long nwords,
                  int F) {
    if (blockIdx.x == 0) {   // dtype detection, single uniform barrier
        __shared__ unsigned s_oz[4], s_sm[4];
        int t = threadIdx.x;
        if (t < 128) {
            long long stride = nwords / 128;
            if (stride < 2) stride = 2;
            long long pos = stride * (long long)t;
            bool odd_zero = true, small = true;
            if (pos + 1 < nwords) {
                unsigned int lo = idx_words[pos & ~1LL];
                unsigned int hi = idx_words[pos | 1LL];
                odd_zero = (hi == 0u);
                small    = (lo < (1u << 24)) && (hi < (1u << 24) || hi == 0u);
            }
            unsigned all_oz = __ballot_sync(0xFFFFFFFFu, odd_zero);
            unsigned all_sm = __ballot_sync(0xFFFFFFFFu, small);
            if ((t & 31) == 0) { s_oz[t >> 5] = all_oz; s_sm[t >> 5] = all_sm; }
        }
        __syncthreads();
        if (t == 0) {
            bool oz = (s_oz[0] & s_oz[1] & s_oz[2] & s_oz[3]) == 0xFFFFFFFFu;
            bool sm = (s_sm[0] & s_sm[1] & s_sm[2] & s_sm[3]) == 0xFFFFFFFFu;
            g_idx_kind = oz ? 0 : (sm ? 1 : 2);
        }
    }

    int f = blockIdx.x * blockDim.x + threadIdx.x;
    if (f >= F) return;
    float2 uv = __ldcs(&uv_face[f]);
    float2 fd = __ldcs(&flux_D[f]);
    float  p  = __ldcs(&p_face[f]);
    float  a  = __ldcs(&face_area[f]);

    float4 rec;
    rec.x = a * uv.x;
    rec.y = a * uv.y;
    rec.z = __uint_as_float(pack_h2(p * a, fminf(1.0f / fmaxf(a, 1e-30f), 65000.0f)));
    rec.w = __uint_as_float(pack_h2(fd.x, fd.y));
    g_rec[f] = rec;   // normal priority: table stays L2-resident
}

__device__ __forceinline__ long long clampF(long long v, long long F) {
    if (v < 0) v = 0;
    if (v >= F) v = F - 1;
    return v;
}

// load indices for adjacent cells (c0=2*idx, c1=2*idx+1) of row r, vectorized
__device__ __forceinline__ void load_idx_pair(const void* p, int kind,
                                              long long rowbase, int idx,
                                              long long F,
                                              long long& iA, long long& iB) {
    if (kind == 0) {
        longlong2 v = __ldcs(&((const longlong2*)((const long long*)p + rowbase))[idx]);
        iA = clampF(v.x, F); iB = clampF(v.y, F);
    } else if (kind == 1) {
        int2 v = __ldcs(&((const int2*)((const int*)p + rowbase))[idx]);
        iA = clampF((long long)v.x, F); iB = clampF((long long)v.y, F);
    } else {
        float2 v = __ldcs(&((const float2*)((const float*)p + rowbase))[idx]);
        iA = clampF((long long)v.x, F); iB = clampF((long long)v.y, F);
    }
}

__global__ void __launch_bounds__(256)
cell_integrate_kernel(const void*   __restrict__ cell_face, // [3, C]
                      const float4* __restrict__ unv4,      // [C,3,2] as float4*
                      const float2* __restrict__ rho2,      // [C] as float2*
                      const float2* __restrict__ rhs2,      // [C] as float2*
                      float*        __restrict__ out,       // [3C]
                      int C, int F) {
    int idx   = blockIdx.x * blockDim.x + threadIdx.x;
    int pairs = C >> 1;                   // C is even (4M); tail handled below
    if (idx >= pairs) return;

    int kind = g_idx_kind;

    long long fA0, fB0, fA1, fB1, fA2, fB2;
    load_idx_pair(cell_face, kind, 0,            idx, F, fA0, fB0);
    load_idx_pair(cell_face, kind, (long long)C, idx, F, fA1, fB1);
    load_idx_pair(cell_face, kind, 2LL * C,      idx, F, fA2, fB2);

    // 6 random gathers in flight, one 32B sector each
    float4 rA0 = __ldcg(&g_rec[fA0]);
    float4 rA1 = __ldcg(&g_rec[fA1]);
    float4 rA2 = __ldcg(&g_rec[fA2]);
    float4 rB0 = __ldcg(&g_rec[fB0]);
    float4 rB1 = __ldcg(&g_rec[fB1]);
    float4 rB2 = __ldcg(&g_rec[fB2]);

    // normals for both cells: 3 vector loads (48B contiguous)
    float4 v0 = __ldcs(&unv4[3 * idx + 0]);  // {nA0.x nA0.y nA1.x nA1.y}
    float4 v1 = __ldcs(&unv4[3 * idx + 1]);  // {nA2.x nA2.y nB0.x nB0.y}
    float4 v2 = __ldcs(&unv4[3 * idx + 2]);  // {nB1.x nB1.y nB2.x nB2.y}

    float2 rhoP = __ldcs(&rho2[idx]);
    float2 rcP  = __ldcs(&rhs2[idx]);

    // ---------------- cell A ----------------
    {
        unsigned z0 = __float_as_uint(rA0.z), w0 = __float_as_uint(rA0.w);
        unsigned z1 = __float_as_uint(rA1.z), w1 = __float_as_uint(rA1.w);
        unsigned z2 = __float_as_uint(rA2.z), w2 = __float_as_uint(rA2.w);

        float de0 = rA0.x * v0.x + rA0.y * v0.y;
        float de1 = rA1.x * v0.z + rA1.y * v0.w;
        float de2 = rA2.x * v1.x + rA2.y * v1.y;
        float lossA = de0 + de1 + de2;

        float s0 = de0 * unpack_hi(z0);
        float s1 = de1 * unpack_hi(z1);
        float s2 = de2 * unpack_hi(z2);
        float Ax = rA0.x * s0 + rA1.x * s1 + rA2.x * s2;
        float Ay = rA0.y * s0 + rA1.y * s1 + rA2.y * s2;

        float q0 = unpack_lo(z0), q1 = unpack_lo(z1), q2 = unpack_lo(z2);
        float Px = q0 * v0.x + q1 * v0.z + q2 * v1.x;
        float Py = q0 * v0.y + q1 * v0.w + q2 * v1.y;

        float Dx = unpack_lo(w0) + unpack_lo(w1) + unpack_lo(w2);
        float Dy = unpack_hi(w0) + unpack_hi(w1) + unpack_hi(w2);

        float inv_rho = 1.0f / rhoP.x;
        float oxA = rcP.x * (-Ax - inv_rho * Px) + Dx;
        float oyA = rcP.x * (-Ay - inv_rho * Py) + Dy;

        // ---------------- cell B ----------------
        unsigned bz0 = __float_as_uint(rB0.z), bw0 = __float_as_uint(rB0.w);
        unsigned bz1 = __float_as_uint(rB1.z), bw1 = __float_as_uint(rB1.w);
        unsigned bz2 = __float_as_uint(rB2.z), bw2 = __float_as_uint(rB2.w);

        float be0 = rB0.x * v1.z + rB0.y * v1.w;
        float be1 = rB1.x * v2.x + rB1.y * v2.y;
        float be2 = rB2.x * v2.z + rB2.y * v2.w;
        float lossB = be0 + be1 + be2;

        float t0 = be0 * unpack_hi(bz0);
        float t1 = be1 * unpack_hi(bz1);
        float t2 = be2 * unpack_hi(bz2);
        float BAx = rB0.x * t0 + rB1.x * t1 + rB2.x * t2;
        float BAy = rB0.y * t0 + rB1.y * t1 + rB2.y * t2;

        float bq0 = unpack_lo(bz0), bq1 = unpack_lo(bz1), bq2 = unpack_lo(bz2);
        float BPx = bq0 * v1.z + bq1 * v2.x + bq2 * v2.z;
        float BPy = bq0 * v1.w + bq1 * v2.y + bq2 * v2.w;

        float BDx = unpack_lo(bw0) + unpack_lo(bw1) + unpack_lo(bw2);
        float BDy = unpack_hi(bw0) + unpack_hi(bw1) + unpack_hi(bw2);

        float inv_rhoB = 1.0f / rhoP.y;
        float oxB = rcP.y * (-BAx - inv_rhoB * BPx) + BDx;
        float oyB = rcP.y * (-BAy - inv_rhoB * BPy) + BDy;

        // vector stores
        __stcs(&((float2*)out)[idx], make_float2(lossA, lossB));      // loss pair
        __stcs(&((float4*)(out + C))[idx], make_float4(oxA, oyA, oxB, oyB));
    }
}

// scalar tail for odd C (not hit for C=4M, kept for safety)
__global__ void cell_tail_kernel(const void* cell_face, const float2* unv,
                                 const float* rho, const float* rhs_coef,
                                 float* out, int C, int F) {
    if (blockIdx.x != 0 || threadIdx.x != 0) return;
    if ((C & 1) == 0) return;
    int c = C - 1;
    int kind = g_idx_kind;
    long long f0, f1, f2;
    if (kind == 0) {
        f0 = ((const long long*)cell_face)[c];
        f1 = ((const long long*)cell_face)[(long long)C + c];
        f2 = ((const long long*)cell_face)[2LL * C + c];
    } else if (kind == 1) {
        f0 = ((const int*)cell_face)[c];
        f1 = ((const int*)cell_face)[(long long)C + c];
        f2 = ((const int*)cell_face)[2LL * C + c];
    } else {
        f0 = (long long)((const float*)cell_face)[c];
        f1 = (long long)((const float*)cell_face)[(long long)C + c];
        f2 = (long long)((const float*)cell_face)[2LL * C + c];
    }
    f0 = clampF(f0, F); f1 = clampF(f1, F); f2 = clampF(f2, F);
    float4 r0 = g_rec[f0], r1 = g_rec[f1], r2 = g_rec[f2];
    float2 n0 = unv[3 * c + 0], n1 = unv[3 * c + 1], n2 = unv[3 * c + 2];
    unsigned z0 = __float_as_uint(r0.z), w0 = __float_as_uint(r0.w);
    unsigned z1 = __float_as_uint(r1.z), w1 = __float_as_uint(r1.w);
    unsigned z2 = __float_as_uint(r2.z), w2 = __float_as_uint(r2.w);
    float de0 = r0.x * n0.x + r0.y * n0.y;
    float de1 = r1.x * n1.x + r1.y * n1.y;
    float de2 = r2.x * n2.x + r2.y * n2.y;
    float s0 = de0 * unpack_hi(z0), s1 = de1 * unpack_hi(z1), s2 = de2 * unpack_hi(z2);
    float Ax = r0.x * s0 + r1.x * s1 + r2.x * s2;
    float Ay = r0.y * s0 + r1.y * s1 + r2.y * s2;
    float Px = unpack_lo(z0) * n0.x + unpack_lo(z1) * n1.x + unpack_lo(z2) * n2.x;
    float Py = unpack_lo(z0) * n0.y + unpack_lo(z1) * n1.y + unpack_lo(z2) * n2.y;
    float Dx = unpack_lo(w0) + unpack_lo(w1) + unpack_lo(w2);
    float Dy = unpack_hi(w0) + unpack_hi(w1) + unpack_hi(w2);
    float inv_rho = 1.0f / rho[c];
    out[c] = de0 + de1 + de2;
    ((float2*)(out + C))[c] = make_float2(rhs_coef[c] * (-Ax - inv_rho * Px) + Dx,
                                          rhs_coef[c] * (-Ay - inv_rho * Py) + Dy);
}

extern "C" void kernel_launch(void* const* d_in, const int* in_sizes, int n_in,
                              void* d_out, int out_size) {
    const float2* uv_face   = (const float2*)d_in[0];
    const float*  p_face    = (const float*) d_in[1];
    const float2* flux_D    = (const float2*)d_in[2];
    const float2* unv       = (const float2*)d_in[3];
    const float*  rho       = (const float*) d_in[4];
    const float*  rhs_coef  = (const float*) d_in[5];
    const float*  face_area = (const float*) d_in[6];
    const void*   cell_face = d_in[7];

    int F = in_sizes[1];   // p_face element count
    int C = in_sizes[4];   // rho element count
    float* out = (float*)d_out;

    long long nwords = 3LL * C;

    const int TPB = 256;
    pack_faces_kernel<<<(F + TPB - 1) / TPB, TPB>>>(uv_face, p_face, flux_D, face_area,
                                                    (const unsigned int*)cell_face,
                                                    nwords, F);
    int pairs = C >> 1;
    cell_integrate_kernel<<<(pairs + TPB - 1) / TPB, TPB>>>(cell_face,
                                                            (const float4*)unv,
                                                            (const float2*)rho,
                                                            (const float2*)rhs_coef,
                                                            out, C, F);
    if (C & 1)
        cell_tail_kernel<<<1, 32>>>(cell_face, unv, rho, rhs_coef, out, C, F);
}